// round 5
// baseline (speedup 1.0000x reference)
#include <cuda_runtime.h>
#include <math_constants.h>

#define BSZ   2
#define TSEQ  2048
#define CDIM  1024
#define HN    16
#define DH    64

// Scratch (allocation-free rule: __device__ globals)
__device__ float g_Q[(size_t)BSZ*HN*TSEQ*DH];   // [B,H,T,D]
__device__ float g_K[(size_t)BSZ*HN*TSEQ*DH];
__device__ float g_V[(size_t)BSZ*HN*TSEQ*DH];
__device__ float g_att[(size_t)BSZ*TSEQ*CDIM];  // [B,T,C]

__device__ __forceinline__ float fast_exp2(float x) {
    float y;
    asm("ex2.approx.f32 %0, %1;" : "=f"(y) : "f"(x));
    return y;
}

// ----------------------------------------------------------------------------
// GEMM-NT: out = A[M,K] @ W[N,K]^T + bias   (M=B*T=4096, N=K=C=1024)
// MODE 0: out[m*N + n]  (row-major [B*T, C])
// MODE 1: head-split layout out[((b*H+h)*T + t)*D + d],  b=m/T, t=m%T, h=n/D, d=n%D
// Block tile 64x64, K-tile 16, 256 threads, 4x4 per-thread micro-tile.
// ----------------------------------------------------------------------------
template <int MODE>
__global__ __launch_bounds__(256)
void gemm_nt_kernel(const float* __restrict__ A,
                    const float* __restrict__ W,
                    const float* __restrict__ bias,
                    float* __restrict__ out)
{
    const int M = BSZ * TSEQ;
    const int N = CDIM;
    const int K = CDIM;

    __shared__ float As[16][72];   // pad 72: conflict-free transposed stores
    __shared__ float Ws[16][72];

    const int tid = threadIdx.x;
    const int m0 = blockIdx.y * 64;
    const int n0 = blockIdx.x * 64;
    const int tm = tid >> 4;       // 0..15
    const int tn = tid & 15;       // 0..15
    const int lr = tid >> 2;       // 0..63 (load row)
    const int lc = (tid & 3) * 4;  // 0,4,8,12 (load k-col)

    float acc[4][4];
#pragma unroll
    for (int i = 0; i < 4; i++)
#pragma unroll
        for (int j = 0; j < 4; j++) acc[i][j] = 0.f;

    const float* Ap = A + (size_t)(m0 + lr) * K + lc;
    const float* Wp = W + (size_t)(n0 + lr) * K + lc;

    for (int k0 = 0; k0 < K; k0 += 16) {
        float4 a4 = *(const float4*)(Ap + k0);
        float4 w4 = *(const float4*)(Wp + k0);
        As[lc + 0][lr] = a4.x; As[lc + 1][lr] = a4.y;
        As[lc + 2][lr] = a4.z; As[lc + 3][lr] = a4.w;
        Ws[lc + 0][lr] = w4.x; Ws[lc + 1][lr] = w4.y;
        Ws[lc + 2][lr] = w4.z; Ws[lc + 3][lr] = w4.w;
        __syncthreads();

#pragma unroll
        for (int k = 0; k < 16; k++) {
            float4 av = *(const float4*)&As[k][tm * 4];
            float4 wv = *(const float4*)&Ws[k][tn * 4];
            float aa[4] = {av.x, av.y, av.z, av.w};
            float ww[4] = {wv.x, wv.y, wv.z, wv.w};
#pragma unroll
            for (int i = 0; i < 4; i++)
#pragma unroll
                for (int j = 0; j < 4; j++)
                    acc[i][j] += aa[i] * ww[j];
        }
        __syncthreads();
    }

    // Epilogue: +bias, vectorized stores (both modes keep d/n contiguous x4)
    const int nbase = n0 + tn * 4;
    float4 bv = *(const float4*)&bias[nbase];
#pragma unroll
    for (int i = 0; i < 4; i++) {
        const int m = m0 + tm * 4 + i;
        float4 v;
        v.x = acc[i][0] + bv.x;
        v.y = acc[i][1] + bv.y;
        v.z = acc[i][2] + bv.z;
        v.w = acc[i][3] + bv.w;
        if (MODE == 0) {
            *(float4*)&out[(size_t)m * N + nbase] = v;
        } else {
            const int b = m >> 11;          // m / TSEQ
            const int t = m & (TSEQ - 1);
            const int h = nbase >> 6;       // n / DH
            const int d = nbase & 63;
            *(float4*)&out[(((size_t)(b * HN + h)) * TSEQ + t) * DH + d] = v;
        }
    }
}

// ----------------------------------------------------------------------------
// Causal flash attention, fp32, online softmax in log2 domain.
// Grid: (T/128, B*H). 128 threads/block, 1 query per thread.
// Key/Value tiles of 64 rows staged in shared; scores in 16-key register chunks.
// ----------------------------------------------------------------------------
#define BQ  128
#define BKT 64

__global__ __launch_bounds__(128)
void flash_attn_kernel(const float* __restrict__ Qg,
                       const float* __restrict__ Kg,
                       const float* __restrict__ Vg,
                       float* __restrict__ att)
{
    const int bh = blockIdx.y;              // 0..B*H-1
    const int q0 = blockIdx.x * BQ;
    const int tid = threadIdx.x;
    const int q = q0 + tid;

    __shared__ float Ks[BKT][DH];
    __shared__ float Vs[BKT][DH];

    // scale = 1/sqrt(D) folded with log2(e) so scores live in log2 domain
    const float qscale = 0.125f * 1.4426950408889634f;

    float qr[DH];
    {
        const float* Qp = Qg + ((size_t)bh * TSEQ + q) * DH;
#pragma unroll
        for (int d4 = 0; d4 < DH / 4; d4++) {
            float4 t = *(const float4*)(Qp + d4 * 4);
            qr[d4 * 4 + 0] = t.x * qscale;
            qr[d4 * 4 + 1] = t.y * qscale;
            qr[d4 * 4 + 2] = t.z * qscale;
            qr[d4 * 4 + 3] = t.w * qscale;
        }
    }

    float o[DH];
#pragma unroll
    for (int d = 0; d < DH; d++) o[d] = 0.f;
    float m = -CUDART_INF_F;
    float l = 0.f;

    const int ntiles = (q0 + BQ - 1) / BKT + 1;   // covers keys <= q0+BQ-1

    for (int kt = 0; kt < ntiles; kt++) {
        const int kbase = kt * BKT;
        __syncthreads();   // previous tile fully consumed
        {
            const int r = tid >> 1;
            const int c = (tid & 1) * 32;
            const float4* kp = (const float4*)(Kg + ((size_t)bh * TSEQ + kbase + r) * DH + c);
            const float4* vp = (const float4*)(Vg + ((size_t)bh * TSEQ + kbase + r) * DH + c);
            float4* ks = (float4*)&Ks[r][c];
            float4* vs = (float4*)&Vs[r][c];
#pragma unroll
            for (int i = 0; i < 8; i++) ks[i] = kp[i];
#pragma unroll
            for (int i = 0; i < 8; i++) vs[i] = vp[i];
        }
        __syncthreads();

#pragma unroll 1
        for (int c = 0; c < BKT; c += 16) {
            float s[16];
            float mt = m;
#pragma unroll
            for (int j = 0; j < 16; j++) {
                const int kk = c + j;
                float acc = 0.f;
#pragma unroll
                for (int d4 = 0; d4 < DH / 4; d4++) {
                    float4 kv = *(const float4*)&Ks[kk][d4 * 4];
                    acc += qr[d4 * 4 + 0] * kv.x;
                    acc += qr[d4 * 4 + 1] * kv.y;
                    acc += qr[d4 * 4 + 2] * kv.z;
                    acc += qr[d4 * 4 + 3] * kv.w;
                }
                s[j] = (kbase + kk <= q) ? acc : -CUDART_INF_F;
                mt = fmaxf(mt, s[j]);
            }
            // mt stays finite after the first chunk (diagonal key always valid);
            // fully-masked later chunks give mt==m -> corr==1, adds nothing.
            const float corr = fast_exp2(m - mt);
            m = mt;
            l *= corr;
#pragma unroll
            for (int d = 0; d < DH; d++) o[d] *= corr;
#pragma unroll
            for (int j = 0; j < 16; j++) {
                const float p = fast_exp2(s[j] - m);
                l += p;
#pragma unroll
                for (int d4 = 0; d4 < DH / 4; d4++) {
                    float4 vv = *(const float4*)&Vs[c + j][d4 * 4];
                    o[d4 * 4 + 0] += p * vv.x;
                    o[d4 * 4 + 1] += p * vv.y;
                    o[d4 * 4 + 2] += p * vv.z;
                    o[d4 * 4 + 3] += p * vv.w;
                }
            }
        }
    }

    const float inv = 1.0f / l;
    const int b = bh / HN;
    const int h = bh % HN;
    float* op = att + ((size_t)(b * TSEQ + q)) * CDIM + h * DH;
#pragma unroll
    for (int d4 = 0; d4 < DH / 4; d4++) {
        float4 v;
        v.x = o[d4 * 4 + 0] * inv;
        v.y = o[d4 * 4 + 1] * inv;
        v.z = o[d4 * 4 + 2] * inv;
        v.w = o[d4 * 4 + 3] * inv;
        *(float4*)(op + d4 * 4) = v;
    }
}

// ----------------------------------------------------------------------------
extern "C" void kernel_launch(void* const* d_in, const int* in_sizes, int n_in,
                              void* d_out, int out_size)
{
    const float* x  = (const float*)d_in[0];
    const float* Wq = (const float*)d_in[1];
    const float* bq = (const float*)d_in[2];
    const float* Wk = (const float*)d_in[3];
    const float* bk = (const float*)d_in[4];
    const float* Wv = (const float*)d_in[5];
    const float* bv = (const float*)d_in[6];
    const float* Wo = (const float*)d_in[7];
    const float* bo = (const float*)d_in[8];
    float* out = (float*)d_out;

    float *Qp, *Kp, *Vp, *Ap;
    cudaGetSymbolAddress((void**)&Qp, g_Q);
    cudaGetSymbolAddress((void**)&Kp, g_K);
    cudaGetSymbolAddress((void**)&Vp, g_V);
    cudaGetSymbolAddress((void**)&Ap, g_att);

    dim3 gemm_grid(CDIM / 64, (BSZ * TSEQ) / 64);   // (16, 64)
    gemm_nt_kernel<1><<<gemm_grid, 256>>>(x, Wq, bq, Qp);
    gemm_nt_kernel<1><<<gemm_grid, 256>>>(x, Wk, bk, Kp);
    gemm_nt_kernel<1><<<gemm_grid, 256>>>(x, Wv, bv, Vp);

    dim3 attn_grid(TSEQ / BQ, BSZ * HN);            // (16, 32)
    flash_attn_kernel<<<attn_grid, 128>>>(Qp, Kp, Vp, Ap);

    gemm_nt_kernel<0><<<gemm_grid, 256>>>(Ap, Wo, bo, out);
}